// round 2
// baseline (speedup 1.0000x reference)
#include <cuda_runtime.h>

// Reference math collapses exactly:
//   p1 has feature dim 1  ->  mu == p1 (exact, mean over a singleton axis)
//   (p1 - mu) == 0 exactly -> var == 0 exactly
//   out = 0/sqrt(eps) * ln_weight + ln_bias = ln_bias  (for ANY x/params/ln_weight)
// So out[b] = ln_bias[0] for all b. We read ln_bias from device memory to stay
// correct for arbitrary bias values.
//
// n = 512 floats = 128 float4. One CTA, 128 threads, one STG.128 each.

__global__ __launch_bounds__(128, 1)
void QuantumGate_65481071410733_kernel(const float* __restrict__ ln_bias,
                                       float4* __restrict__ out) {
    float b = __ldg(ln_bias);
    out[threadIdx.x] = make_float4(b, b, b, b);
}

extern "C" void kernel_launch(void* const* d_in, const int* in_sizes, int n_in,
                              void* d_out, int out_size) {
    // Input order per metadata: x, params, ln_weight, ln_bias
    const float* ln_bias = (const float*)d_in[3];
    // out_size == 512, 16B-aligned harness allocation -> 128 float4 stores
    QuantumGate_65481071410733_kernel<<<1, 128>>>(ln_bias, (float4*)d_out);
}

// round 3
// speedup vs baseline: 4.4476x; 4.4476x over previous
#include <cuda_runtime.h>

// Reference math collapses exactly:
//   p1 has feature dim 1  ->  mu == p1 (exact, mean over a singleton axis)
//   (p1 - mu) == 0 exactly -> var == 0 exactly
//   out = 0/sqrt(eps) * ln_weight + ln_bias = ln_bias  (for ANY x/params/ln_weight)
// So out[b] = ln_bias[0] for all b. We read ln_bias from device memory to stay
// correct for arbitrary bias values.
//
// Shape chosen empirically: grid=2 x 256 scalar stores measured 4.608 us
// (R1); the grid=1 x 128 float4 variant had a faster kernel node (3.616 us)
// but a 20 us harness wall-time outlier, so we pin the known-good config.

__global__ __launch_bounds__(256, 1)
void QuantumGate_65481071410733_kernel(const float* __restrict__ ln_bias,
                                       float* __restrict__ out,
                                       int n) {
    int i = blockIdx.x * blockDim.x + threadIdx.x;
    if (i < n) {
        out[i] = __ldg(ln_bias);
    }
}

extern "C" void kernel_launch(void* const* d_in, const int* in_sizes, int n_in,
                              void* d_out, int out_size) {
    // Input order per metadata: x, params, ln_weight, ln_bias
    const float* ln_bias = (const float*)d_in[3];
    float* out = (float*)d_out;
    int n = out_size;  // 512
    QuantumGate_65481071410733_kernel<<<(n + 255) / 256, 256>>>(ln_bias, out, n);
}